// round 9
// baseline (speedup 1.0000x reference)
#include <cuda_runtime.h>

// Problem dims (fixed by the reference)
#define BB  2
#define SS  2048
#define DD  1024
#define HH  16
#define HD  64
#define MM  (BB*SS)          // 4096 rows for the projections

// ---------------------------------------------------------------------------
// Scratch (device globals -- no cudaMalloc allowed)
// ---------------------------------------------------------------------------
__device__ float g_Q[BB*HH*SS*HD];     // [B,H,S,Hd], pre-scaled by 1/sqrt(Hd)
__device__ float g_K[BB*HH*SS*HD];     // [B,H,S,Hd]
__device__ float g_V[BB*HH*SS*HD];     // [B,H,S,Hd]
__device__ float g_attn[BB*SS*DD];     // [B,S,H*Hd]  (ready for out-proj)
__device__ float g_vsum[BB*HH*HD];     // per-(b,h) sum over k of V

// ---------------------------------------------------------------------------
// SGEMM: Y = (X @ W^T + bias) * scale
//   X: [M,K] row-major, W: [N,K] row-major (torch Linear weight)
// MODE 0: Y row-major [M,N]
// MODE 1: Y scattered to [B,H,S,Hd]  (m=b*S+s, n=h*64+hd)
// Tiles: 128x128x16, 256 threads, 8x8 per thread.
// ---------------------------------------------------------------------------
template<int MODE>
__global__ __launch_bounds__(256)
void sgemm_xwT(const float* __restrict__ X, const float* __restrict__ W,
               const float* __restrict__ bias, float* __restrict__ Y,
               int M, int N, int K, float scale)
{
    __shared__ float As[16][128];
    __shared__ float Bs[16][128];

    const int tid = threadIdx.x;
    const int tx  = tid & 15;        // -> n
    const int ty  = tid >> 4;        // -> m
    const int m0  = blockIdx.y * 128;
    const int n0  = blockIdx.x * 128;

    float acc[8][8];
#pragma unroll
    for (int i = 0; i < 8; i++)
#pragma unroll
        for (int j = 0; j < 8; j++) acc[i][j] = 0.f;

    for (int k0 = 0; k0 < K; k0 += 16) {
        __syncthreads();
        // cooperative load: 128x16 of X and W, as float4
#pragma unroll
        for (int r = 0; r < 2; r++) {
            int idx = tid + r * 256;          // 0..511
            int mm  = idx >> 2;               // 0..127
            int kq  = idx & 3;                // 0..3 (quad of 4 K-values)
            float4 va = *reinterpret_cast<const float4*>(
                &X[(size_t)(m0 + mm) * K + k0 + kq * 4]);
            As[kq*4+0][mm] = va.x; As[kq*4+1][mm] = va.y;
            As[kq*4+2][mm] = va.z; As[kq*4+3][mm] = va.w;
            float4 vb = *reinterpret_cast<const float4*>(
                &W[(size_t)(n0 + mm) * K + k0 + kq * 4]);
            Bs[kq*4+0][mm] = vb.x; Bs[kq*4+1][mm] = vb.y;
            Bs[kq*4+2][mm] = vb.z; Bs[kq*4+3][mm] = vb.w;
        }
        __syncthreads();

#pragma unroll
        for (int kk = 0; kk < 16; kk++) {
            float a[8], b[8];
#pragma unroll
            for (int i = 0; i < 8; i += 4) {
                float4 t = *reinterpret_cast<const float4*>(&As[kk][ty*8 + i]);
                a[i] = t.x; a[i+1] = t.y; a[i+2] = t.z; a[i+3] = t.w;
            }
#pragma unroll
            for (int j = 0; j < 8; j += 4) {
                float4 t = *reinterpret_cast<const float4*>(&Bs[kk][tx*8 + j]);
                b[j] = t.x; b[j+1] = t.y; b[j+2] = t.z; b[j+3] = t.w;
            }
#pragma unroll
            for (int i = 0; i < 8; i++)
#pragma unroll
                for (int j = 0; j < 8; j++)
                    acc[i][j] += a[i] * b[j];
        }
    }

    // epilogue
    const int nb = n0 + tx * 8;
    float bi[8];
#pragma unroll
    for (int j = 0; j < 8; j++) bi[j] = bias[nb + j];

#pragma unroll
    for (int i = 0; i < 8; i++) {
        int m = m0 + ty * 8 + i;
        float out[8];
#pragma unroll
        for (int j = 0; j < 8; j++) out[j] = (acc[i][j] + bi[j]) * scale;

        float* dst;
        if (MODE == 0) {
            dst = &Y[(size_t)m * N + nb];
        } else {
            int b = m / SS, s = m - b * SS;
            int h = nb >> 6, hdo = nb & 63;   // nb%64..+7 never crosses a head
            dst = &Y[(((size_t)(b * HH + h)) * SS + s) * HD + hdo];
        }
        *reinterpret_cast<float4*>(dst)     = make_float4(out[0], out[1], out[2], out[3]);
        *reinterpret_cast<float4*>(dst + 4) = make_float4(out[4], out[5], out[6], out[7]);
    }
}

// ---------------------------------------------------------------------------
// Per-(b,h) column sums of V -> g_vsum
// ---------------------------------------------------------------------------
__global__ void vsum_kernel(const float* __restrict__ V, float* __restrict__ vs)
{
    int bh = blockIdx.x;
    int j  = threadIdx.x;                  // 0..63
    const float* base = &V[(size_t)bh * SS * HD + j];
    float s = 0.f;
    for (int k = 0; k < SS; k++) s += base[(size_t)k * HD];
    vs[bh * HD + j] = s;
}

// ---------------------------------------------------------------------------
// Streaming evidence-attention (flash-style, no max needed).
// Q already carries the 1/sqrt(Hd) scale.
// grid: (S/128, B*H), 128 threads; each thread owns one q row.
// ---------------------------------------------------------------------------
__global__ __launch_bounds__(128)
void attn_kernel(const float* __restrict__ Q, const float* __restrict__ K,
                 const float* __restrict__ V, const float* __restrict__ vsum,
                 const float* __restrict__ es_p, const float* __restrict__ eb_p,
                 float* __restrict__ attn_out, float* __restrict__ unc_out)
{
    const int KT = 32;
    __shared__ float Ks[KT][HD];
    __shared__ float Vs[KT][HD];

    const int tid = threadIdx.x;
    const int bh  = blockIdx.y;
    const int q   = blockIdx.x * 128 + tid;

    // Q row into registers (16 float4 = 64 floats)
    float4 qr[16];
    {
        const float4* qp = reinterpret_cast<const float4*>(
            &Q[((size_t)bh * SS + q) * HD]);
#pragma unroll
        for (int i = 0; i < 16; i++) qr[i] = qp[i];
    }

    float4 acc[16];
#pragma unroll
    for (int i = 0; i < 16; i++) acc[i] = make_float4(0.f, 0.f, 0.f, 0.f);
    float E = 0.f;

    const float* kbase = &K[(size_t)bh * SS * HD];
    const float* vbase = &V[(size_t)bh * SS * HD];

    for (int k0 = 0; k0 < SS; k0 += KT) {
        __syncthreads();
        // load K/V tile: KT*64 floats each = 512 float4 each, 128 threads
#pragma unroll
        for (int r = 0; r < 4; r++) {
            int idx  = tid + r * 128;        // 0..511
            int row  = idx >> 4;             // 0..31
            int quad = idx & 15;             // 0..15
            *reinterpret_cast<float4*>(&Ks[row][quad * 4]) =
                *reinterpret_cast<const float4*>(&kbase[(size_t)(k0 + row) * HD + quad * 4]);
            *reinterpret_cast<float4*>(&Vs[row][quad * 4]) =
                *reinterpret_cast<const float4*>(&vbase[(size_t)(k0 + row) * HD + quad * 4]);
        }
        __syncthreads();

#pragma unroll 4
        for (int kk = 0; kk < KT; kk++) {
            float s = 0.f;
#pragma unroll
            for (int i = 0; i < 16; i++) {
                float4 kv = *reinterpret_cast<const float4*>(&Ks[kk][i * 4]);
                s += qr[i].x * kv.x + qr[i].y * kv.y + qr[i].z * kv.z + qr[i].w * kv.w;
            }
            float p = __expf(s);
            E += p;
#pragma unroll
            for (int i = 0; i < 16; i++) {
                float4 vv = *reinterpret_cast<const float4*>(&Vs[kk][i * 4]);
                acc[i].x += p * vv.x; acc[i].y += p * vv.y;
                acc[i].z += p * vv.z; acc[i].w += p * vv.w;
            }
        }
    }

    const float es   = *es_p;
    const float c    = 1.0f + *eb_p;
    const float den  = es * E + c * (float)SS;
    const float inv  = 1.0f / den;

    const int b = bh / HH, h = bh % HH;
    const float4* vsv = reinterpret_cast<const float4*>(&vsum[bh * HD]);
    float4* dst = reinterpret_cast<float4*>(
        &attn_out[(((size_t)b * SS + q) * HH + h) * HD]);
#pragma unroll
    for (int i = 0; i < 16; i++) {
        float4 vs4 = vsv[i];
        float4 o;
        o.x = (es * acc[i].x + c * vs4.x) * inv;
        o.y = (es * acc[i].y + c * vs4.y) * inv;
        o.z = (es * acc[i].z + c * vs4.z) * inv;
        o.w = (es * acc[i].w + c * vs4.w) * inv;
        dst[i] = o;
    }
    unc_out[(size_t)bh * SS + q] = (float)SS * inv;
}

// ---------------------------------------------------------------------------
// kernel_launch
// inputs: x, q_w, q_b, k_w, k_b, v_w, v_b, out_w, out_b, evidence_scale, evidence_bias
// output: concat(output[B,S,D], uncertainty[B,H,S])  (fp32)
// ---------------------------------------------------------------------------
extern "C" void kernel_launch(void* const* d_in, const int* in_sizes, int n_in,
                              void* d_out, int out_size)
{
    const float* x     = (const float*)d_in[0];
    const float* q_w   = (const float*)d_in[1];
    const float* q_b   = (const float*)d_in[2];
    const float* k_w   = (const float*)d_in[3];
    const float* k_b   = (const float*)d_in[4];
    const float* v_w   = (const float*)d_in[5];
    const float* v_b   = (const float*)d_in[6];
    const float* out_w = (const float*)d_in[7];
    const float* out_b = (const float*)d_in[8];
    const float* es    = (const float*)d_in[9];
    const float* eb    = (const float*)d_in[10];
    float* out = (float*)d_out;

    float *Qb, *Kb, *Vb, *Ab, *VS;
    cudaGetSymbolAddress((void**)&Qb, g_Q);
    cudaGetSymbolAddress((void**)&Kb, g_K);
    cudaGetSymbolAddress((void**)&Vb, g_V);
    cudaGetSymbolAddress((void**)&Ab, g_attn);
    cudaGetSymbolAddress((void**)&VS, g_vsum);

    const float inv_sqrt_hd = 0.125f;   // 1/sqrt(64), folded into Q

    dim3 gemm_grid(DD / 128, MM / 128); // (8, 32)
    sgemm_xwT<1><<<gemm_grid, 256>>>(x, q_w, q_b, Qb, MM, DD, DD, inv_sqrt_hd);
    sgemm_xwT<1><<<gemm_grid, 256>>>(x, k_w, k_b, Kb, MM, DD, DD, 1.0f);
    sgemm_xwT<1><<<gemm_grid, 256>>>(x, v_w, v_b, Vb, MM, DD, DD, 1.0f);

    vsum_kernel<<<BB * HH, HD>>>(Vb, VS);

    dim3 attn_grid(SS / 128, BB * HH);  // (16, 32)
    attn_kernel<<<attn_grid, 128>>>(Qb, Kb, Vb, VS, es, eb,
                                    Ab, out + (size_t)BB * SS * DD);

    sgemm_xwT<0><<<gemm_grid, 256>>>(Ab, out_w, out_b, out, MM, DD, DD, 1.0f);
}